// round 14
// baseline (speedup 1.0000x reference)
#include <cuda_runtime.h>
#include <cuda_bf16.h>
#include <math.h>
#include <stdint.h>

typedef unsigned long long ull;

#define T_STEPS 64
#define BATCH   32
#define VOCAB   32000
#define HDIM    512
#define G4      2048
#define MTOT    (T_STEPS * BATCH)   // 2048
#define KX      1536                // 3 * HDIM (bf16x3 folded K)

// ---------------- scratch (static __device__, allocation-free) ----------------
__device__ float  g_XPt[(size_t)T_STEPS * G4 * BATCH];     // [t][g][b] input proj + biases
__device__ float4 g_hT4[2][128 * 32];                      // [k4][b] hidden, float4 over k
__device__ float  g_cT[HDIM * BATCH];                      // [j][b] cell state
__device__ float  g_H[(size_t)MTOT * HDIM];                // [i][k] tentative hidden
__device__ float4 g_W4[HDIM * HDIM];                       // [j][k] -> (wi, wf, wg, wo)
__device__ __align__(16) __nv_bfloat16 g_HX[(size_t)MTOT * KX];    // [i][hi|hi|lo]
__device__ __align__(16) __nv_bfloat16 g_WX[(size_t)VOCAB * KX];   // [v][hi|lo|hi]
__device__ __align__(16) __nv_bfloat16 g_EX[(size_t)MTOT * KX];    // emb[tok[i]] split
__device__ __align__(16) __nv_bfloat16 g_WIX[(size_t)G4 * KX];     // W_ih split

// ---------------- helpers ----------------
__device__ __forceinline__ ull pack2(float lo, float hi) {
    ull r; asm("mov.b64 %0, {%1, %2};" : "=l"(r) : "f"(lo), "f"(hi)); return r;
}
__device__ __forceinline__ void unpack2(ull v, float& lo, float& hi) {
    unsigned a, b; asm("mov.b64 {%0, %1}, %2;" : "=r"(a), "=r"(b) : "l"(v));
    lo = __uint_as_float(a); hi = __uint_as_float(b);
}
__device__ __forceinline__ void ffma2(ull& acc, ull a, ull b) {
    asm("fma.rn.f32x2 %0, %1, %2, %0;" : "+l"(acc) : "l"(a), "l"(b));
}
__device__ __forceinline__ ull d2u(double d) { return (ull)__double_as_longlong(d); }
__device__ __forceinline__ uint32_t smem_u32(const void* p) {
    uint32_t a;
    asm("{ .reg .u64 t; cvta.to.shared.u64 t, %1; cvt.u32.u64 %0, t; }" : "=r"(a) : "l"(p));
    return a;
}
__device__ __forceinline__ void cp16(uint32_t saddr, const void* gaddr) {
    asm volatile("cp.async.cg.shared.global [%0], [%1], 16;" :: "r"(saddr), "l"(gaddr));
}
__device__ __forceinline__ uint4 ldsm_x4(uint32_t addr) {
    uint4 r;
    asm volatile("ldmatrix.sync.aligned.m8n8.x4.shared.b16 {%0,%1,%2,%3}, [%4];"
                 : "=r"(r.x), "=r"(r.y), "=r"(r.z), "=r"(r.w) : "r"(addr));
    return r;
}
__device__ __forceinline__ void mma16816(float* c, uint4 a, uint32_t b0, uint32_t b1) {
    asm volatile(
        "mma.sync.aligned.m16n8k16.row.col.f32.bf16.bf16.f32 "
        "{%0,%1,%2,%3}, {%4,%5,%6,%7}, {%8,%9}, {%0,%1,%2,%3};"
        : "+f"(c[0]), "+f"(c[1]), "+f"(c[2]), "+f"(c[3])
        : "r"(a.x), "r"(a.y), "r"(a.z), "r"(a.w), "r"(b0), "r"(b1));
}

// ================= HMMA GEMM: C[M x N] = A . B^T (+bias), folded K'=1536 =================
// CTA tile 128m x 256n, 512 threads (16 warps = 2m x 8n, warp tile 64x32), 3-stage pipeline.
// A/B operands selected INSIDE the kernel (never pass __device__ globals from host!).
// EPI 0: A=g_HX, B=g_WX, out = logits + b_fc.   EPI 1: A=g_EX, B=g_WIX, -> g_XPt + b_ih+b_hh.
#define A_STAGE 16384                 // 128 rows x 32B x 4 planes
#define B_STAGE 32768                 // 256 rows x 32B x 4 planes
#define STAGE_B (A_STAGE + B_STAGE)   // 48KB
#define NPIPE   3
#define GEMM_SMEM (NPIPE * STAGE_B)   // 144KB
#define NSTAGE 24

template <int EPI>
__global__ void __launch_bounds__(512, 1)
mma_gemm(const float* __restrict__ bias0,
         const float* __restrict__ bias1,
         float* __restrict__ out) {
    const __nv_bfloat16* __restrict__ Asrc = (EPI == 0) ? g_HX : g_EX;
    const __nv_bfloat16* __restrict__ Bsrc = (EPI == 0) ? g_WX : g_WIX;

    extern __shared__ char sm[];
    uint32_t smb = smem_u32(sm);
    int tid = threadIdx.x, wid = tid >> 5, lane = tid & 31;
    int i0 = blockIdx.x * 128;
    int v0 = blockIdx.y * 256;
    int m0w = (wid & 1) * 64;          // warp m offset (2 groups)
    int n0w = (wid >> 1) * 32;         // warp n offset (8 groups, 0..224)

    // loader: 512 threads x (2 A rows + 4 B rows) of one 16B chunk each per stage
    int lrow = tid >> 3, lseg = tid & 7;          // lrow 0..63, lseg 0..7
    int lplane = lseg >> 1, lhalf = lseg & 1;
    const __nv_bfloat16* gA = Asrc + (size_t)(i0 + lrow) * KX + lseg * 8;
    const __nv_bfloat16* gB = Bsrc + (size_t)(v0 + lrow) * KX + lseg * 8;

    auto issue_stage = [&](int s) {
        uint32_t sb = (uint32_t)((s % NPIPE) * STAGE_B);
        size_t gk = (size_t)s * 64;
#pragma unroll
        for (int i = 0; i < 2; i++) {   // A rows: lrow, lrow+64
            uint32_t ro = (uint32_t)(lplane * 4096)
                        + (uint32_t)(((lrow + i * 64 + lplane) & 127) * 32)
                        + (uint32_t)(lhalf * 16);
            cp16(smb + sb + ro, gA + gk + (size_t)i * 64 * KX);
        }
#pragma unroll
        for (int i = 0; i < 4; i++) {   // B rows: lrow, +64, +128, +192
            uint32_t ro = (uint32_t)(A_STAGE + lplane * 8192)
                        + (uint32_t)(((lrow + i * 64 + lplane) & 255) * 32)
                        + (uint32_t)(lhalf * 16);
            cp16(smb + sb + ro, gB + gk + (size_t)i * 64 * KX);
        }
        asm volatile("cp.async.commit_group;");
    };

    float acc[4][4][4];
#pragma unroll
    for (int a = 0; a < 4; a++)
#pragma unroll
        for (int b = 0; b < 4; b++)
#pragma unroll
            for (int r = 0; r < 4; r++) acc[a][b][r] = 0.0f;

    issue_stage(0);
    issue_stage(1);
    issue_stage(2);

    for (int s = 0; s < NSTAGE; s++) {
        asm volatile("cp.async.wait_group 2;");
        __syncthreads();
        uint32_t base = smb + (uint32_t)((s % NPIPE) * STAGE_B);
#pragma unroll
        for (int p = 0; p < 4; p++) {
            uint32_t abase = base + p * 4096;
            uint32_t bbase = base + A_STAGE + p * 8192;
            uint32_t brow0 = (uint32_t)(n0w + (lane & 7) + ((lane >> 4) << 3));
            uint32_t bhalf = (uint32_t)((lane >> 3) & 1);
            uint4 bf01 = ldsm_x4(bbase + (((brow0 + p) & 255) * 32) + bhalf * 16);
            uint4 bf23 = ldsm_x4(bbase + (((brow0 + 16 + p) & 255) * 32) + bhalf * 16);
            uint32_t arow = (uint32_t)(m0w + (lane & 15));
            uint32_t ahalf = (uint32_t)(lane >> 4);
            uint4 af[4];
#pragma unroll
            for (int im = 0; im < 4; im++)
                af[im] = ldsm_x4(abase + (((arow + im * 16 + p) & 127) * 32) + ahalf * 16);
#pragma unroll
            for (int im = 0; im < 4; im++) {
                mma16816(acc[im][0], af[im], bf01.x, bf01.y);
                mma16816(acc[im][1], af[im], bf01.z, bf01.w);
                mma16816(acc[im][2], af[im], bf23.x, bf23.y);
                mma16816(acc[im][3], af[im], bf23.z, bf23.w);
            }
        }
        __syncthreads();
        if (s + NPIPE < NSTAGE) issue_stage(s + NPIPE);
        else asm volatile("cp.async.commit_group;");
    }

    // ---------------- epilogue ----------------
    int gm = lane >> 2, gn = 2 * (lane & 3);
    if (EPI == 0) {
#pragma unroll
        for (int im = 0; im < 4; im++) {
#pragma unroll
            for (int jn = 0; jn < 4; jn++) {
                int col = v0 + n0w + jn * 8 + gn;
                float2 bb = *(const float2*)(bias0 + col);
                int row = i0 + m0w + im * 16 + gm;
                float2 o0 = make_float2(acc[im][jn][0] + bb.x, acc[im][jn][1] + bb.y);
                float2 o1 = make_float2(acc[im][jn][2] + bb.x, acc[im][jn][3] + bb.y);
                __stcs((float2*)(out + (size_t)row * VOCAB + col), o0);
                __stcs((float2*)(out + (size_t)(row + 8) * VOCAB + col), o1);
            }
        }
    } else {
#pragma unroll
        for (int im = 0; im < 4; im++) {
#pragma unroll
            for (int jn = 0; jn < 4; jn++) {
                int col = v0 + n0w + jn * 8 + gn;
                float b0 = bias0[col] + bias1[col];
                float b1 = bias0[col + 1] + bias1[col + 1];
                int r0 = i0 + m0w + im * 16 + gm;
                int r1 = r0 + 8;
                size_t base0 = (size_t)(r0 >> 5) * (G4 * BATCH) + (r0 & 31);
                size_t base1 = (size_t)(r1 >> 5) * (G4 * BATCH) + (r1 & 31);
                g_XPt[base0 + (size_t)col * 32]       = acc[im][jn][0] + b0;
                g_XPt[base0 + (size_t)(col + 1) * 32] = acc[im][jn][1] + b1;
                g_XPt[base1 + (size_t)col * 32]       = acc[im][jn][2] + b0;
                g_XPt[base1 + (size_t)(col + 1) * 32] = acc[im][jn][3] + b1;
            }
        }
    }
}

// ================= split kernels (fp32 -> bf16 hi/lo, folded-K layout) =================
// A-side layout: [hi | hi | lo].  B-side layout: [hi | lo | hi].
__device__ __forceinline__ void split_row(const float4 w, __nv_bfloat16* row, int k, bool aside) {
    __nv_bfloat16 h0 = __float2bfloat16_rn(w.x), h1 = __float2bfloat16_rn(w.y);
    __nv_bfloat16 h2 = __float2bfloat16_rn(w.z), h3 = __float2bfloat16_rn(w.w);
    __nv_bfloat16 l0 = __float2bfloat16_rn(w.x - __bfloat162float(h0));
    __nv_bfloat16 l1 = __float2bfloat16_rn(w.y - __bfloat162float(h1));
    __nv_bfloat16 l2 = __float2bfloat16_rn(w.z - __bfloat162float(h2));
    __nv_bfloat16 l3 = __float2bfloat16_rn(w.w - __bfloat162float(h3));
    ushort4 hv = make_ushort4(__bfloat16_as_ushort(h0), __bfloat16_as_ushort(h1),
                              __bfloat16_as_ushort(h2), __bfloat16_as_ushort(h3));
    ushort4 lv = make_ushort4(__bfloat16_as_ushort(l0), __bfloat16_as_ushort(l1),
                              __bfloat16_as_ushort(l2), __bfloat16_as_ushort(l3));
    *(ushort4*)(row + k) = hv;
    if (aside) {
        *(ushort4*)(row + 512 + k)  = hv;
        *(ushort4*)(row + 1024 + k) = lv;
    } else {
        *(ushort4*)(row + 512 + k)  = lv;
        *(ushort4*)(row + 1024 + k) = hv;
    }
}

__global__ void split_W(const float* __restrict__ W_fc) {
    int idx = blockIdx.x * 256 + threadIdx.x;        // 32000*128
    int v = idx >> 7, q = idx & 127;
    float4 w = *(const float4*)(W_fc + (size_t)v * HDIM + q * 4);
    split_row(w, g_WX + (size_t)v * KX, q * 4, false);
}
__global__ void split_WI(const float* __restrict__ W_ih) {
    int idx = blockIdx.x * 256 + threadIdx.x;        // 2048*128
    int v = idx >> 7, q = idx & 127;
    float4 w = *(const float4*)(W_ih + (size_t)v * HDIM + q * 4);
    split_row(w, g_WIX + (size_t)v * KX, q * 4, false);
}
__global__ void split_E(const int* __restrict__ tokens, const float* __restrict__ emb) {
    int idx = blockIdx.x * 256 + threadIdx.x;        // 2048*128
    int i = idx >> 7, q = idx & 127;
    int tok = tokens[i];
    float4 w = *(const float4*)(emb + (size_t)tok * HDIM + q * 4);
    split_row(w, g_EX + (size_t)i * KX, q * 4, true);
}
__global__ void split_H(void) {
    int idx = blockIdx.x * 256 + threadIdx.x;        // 2048*128
    int i = idx >> 7, q = idx & 127;
    float4 w = *(const float4*)(g_H + (size_t)i * HDIM + q * 4);
    split_row(w, g_HX + (size_t)i * KX, q * 4, true);
}

// ================= one-time W_hh transpose =================
__global__ void prep_W4(const float* __restrict__ W_hh) {
    int idx = blockIdx.x * 256 + threadIdx.x;
    int j = idx >> 9, k = idx & 511;
    g_W4[(size_t)j * 512 + k] = make_float4(
        W_hh[(size_t)(0 * 512 + j) * 512 + k],
        W_hh[(size_t)(1 * 512 + j) * 512 + k],
        W_hh[(size_t)(2 * 512 + j) * 512 + k],
        W_hh[(size_t)(3 * 512 + j) * 512 + k]);
}

// ================= init =================
__global__ void init_kernel(const float* __restrict__ h0, const float* __restrict__ c0) {
    int idx = blockIdx.x * blockDim.x + threadIdx.x;
    if (idx < BATCH * HDIM) {
        int j = idx >> 5, b = idx & 31;
        ((float*)g_hT4[0])[(j >> 2) * 128 + b * 4 + (j & 3)] = h0[b * HDIM + j];
        g_cT[j * 32 + b] = c0[b * HDIM + j];
    }
}

// ================= recurrent step: K-split x8, CTA = one j (R13-proven) =================
__global__ void __launch_bounds__(256, 4)
recurrent_kernel(const int* __restrict__ tokens, int t) {
    __shared__ float4 sred[8][32];
    int tid = threadIdx.x;
    int w = tid >> 5, b = tid & 31;
    int j = blockIdx.x;

    const float4*  hT = g_hT4[t & 1];
    const double2* wp = (const double2*)(g_W4 + (size_t)j * 512) + (size_t)w * 64;
    const float4*  hp = hT + w * 16 * 32;

    ull aif0 = pack2(0.0f, 0.0f), aif1 = pack2(0.0f, 0.0f);
    ull ago0 = pack2(0.0f, 0.0f), ago1 = pack2(0.0f, 0.0f);

#pragma unroll
    for (int kk = 0; kk < 16; kk++) {
        float4  h4 = hp[kk * 32 + b];
        double2 w0 = wp[kk * 4 + 0];
        double2 w1 = wp[kk * 4 + 1];
        double2 w2 = wp[kk * 4 + 2];
        double2 w3 = wp[kk * 4 + 3];
        ull hx = pack2(h4.x, h4.x), hy = pack2(h4.y, h4.y);
        ull hz = pack2(h4.z, h4.z), hw = pack2(h4.w, h4.w);
        ffma2(aif0, hx, d2u(w0.x));
        ffma2(ago0, hx, d2u(w0.y));
        ffma2(aif1, hy, d2u(w1.x));
        ffma2(ago1, hy, d2u(w1.y));
        ffma2(aif0, hz, d2u(w2.x));
        ffma2(ago0, hz, d2u(w2.y));
        ffma2(aif1, hw, d2u(w3.x));
        ffma2(ago1, hw, d2u(w3.y));
    }

    float ia, fa, ib, fb, ga, oa, gb, ob;
    unpack2(aif0, ia, fa); unpack2(aif1, ib, fb);
    unpack2(ago0, ga, oa); unpack2(ago1, gb, ob);
    sred[w][b] = make_float4(ia + ib, fa + fb, ga + gb, oa + ob);
    __syncthreads();

    if (w == 0) {
        float4 acc4 = sred[0][b];
#pragma unroll
        for (int q = 1; q < 8; q++) {
            float4 s = sred[q][b];
            acc4.x += s.x; acc4.y += s.y; acc4.z += s.z; acc4.w += s.w;
        }
        size_t xb = (size_t)t * (G4 * BATCH) + (size_t)b;
        float ig = acc4.x + g_XPt[xb + (size_t)(0 * 512 + j) * 32];
        float fg = acc4.y + g_XPt[xb + (size_t)(1 * 512 + j) * 32];
        float gg = acc4.z + g_XPt[xb + (size_t)(2 * 512 + j) * 32];
        float og = acc4.w + g_XPt[xb + (size_t)(3 * 512 + j) * 32];

        float iv = 1.0f / (1.0f + expf(-ig));
        float fv = 1.0f / (1.0f + expf(-fg));
        float gv = tanhf(gg);
        float ov = 1.0f / (1.0f + expf(-og));

        float cold = g_cT[j * 32 + b];
        float ctmp = fv * cold + iv * gv;
        float htmp = ov * tanhf(ctmp);
        bool  msk  = tokens[t * BATCH + b] != 0;   // PAD = 0

        g_H[((size_t)t * BATCH + b) * HDIM + j] = htmp;
        float hold = ((const float*)hT)[(j >> 2) * 128 + b * 4 + (j & 3)];
        ((float*)g_hT4[(t + 1) & 1])[(j >> 2) * 128 + b * 4 + (j & 3)] = msk ? htmp : hold;
        g_cT[j * 32 + b] = msk ? ctmp : cold;
    }
}

// ================= launch =================
extern "C" void kernel_launch(void* const* d_in, const int* in_sizes, int n_in,
                              void* d_out, int out_size) {
    const int*   tokens = (const int*)d_in[0];
    const float* emb    = (const float*)d_in[1];
    const float* W_ih   = (const float*)d_in[2];
    const float* W_hh   = (const float*)d_in[3];
    const float* b_ih   = (const float*)d_in[4];
    const float* b_hh   = (const float*)d_in[5];
    const float* W_fc   = (const float*)d_in[6];
    const float* b_fc   = (const float*)d_in[7];
    const float* h0     = (const float*)d_in[8];
    const float* c0     = (const float*)d_in[9];
    float* out = (float*)d_out;

    cudaFuncSetAttribute(mma_gemm<0>, cudaFuncAttributeMaxDynamicSharedMemorySize, GEMM_SMEM);
    cudaFuncSetAttribute(mma_gemm<1>, cudaFuncAttributeMaxDynamicSharedMemorySize, GEMM_SMEM);

    init_kernel<<<64, 256>>>(h0, c0);
    prep_W4<<<1024, 256>>>(W_hh);
    split_W<<<16000, 256>>>(W_fc);
    split_WI<<<1024, 256>>>(W_ih);
    split_E<<<1024, 256>>>(tokens, emb);

    // XPt = emb[tok] @ W_ih^T + (b_ih + b_hh):  M=2048, N=2048, K'=1536 (HMMA bf16x3)
    mma_gemm<1><<<dim3(16, 8), 512, GEMM_SMEM>>>(b_ih, b_hh, nullptr);

    // 64 LSTM steps, one launch each (proven kernel)
    for (int t = 0; t < T_STEPS; t++)
        recurrent_kernel<<<512, 256>>>(tokens, t);

    split_H<<<1024, 256>>>();

    // out = HX @ WX^T + b_fc:  M=2048, N=32000, K'=1536 (HMMA bf16x3, 128x256 tiles)
    mma_gemm<0><<<dim3(16, 125), 512, GEMM_SMEM>>>(b_fc, nullptr, out);
}

// round 15
// speedup vs baseline: 1.0496x; 1.0496x over previous
#include <cuda_runtime.h>
#include <cuda_bf16.h>
#include <math.h>
#include <stdint.h>

typedef unsigned long long ull;

#define T_STEPS 64
#define BATCH   32
#define VOCAB   32000
#define HDIM    512
#define G4      2048
#define MTOT    (T_STEPS * BATCH)   // 2048
#define KXS     1024                // stored bf16 cols: [hi(512) | lo(512)]

// ---------------- scratch (static __device__, allocation-free) ----------------
__device__ float  g_XPt[(size_t)T_STEPS * G4 * BATCH];     // [t][g][b] input proj + biases
__device__ float4 g_hT4[2][128 * 32];                      // [k4][b] hidden, float4 over k
__device__ float  g_cT[HDIM * BATCH];                      // [j][b] cell state
__device__ float4 g_W4[HDIM * HDIM];                       // [j][k] -> (wi, wf, wg, wo)
__device__ __align__(16) __nv_bfloat16 g_HX[(size_t)MTOT * KXS];    // H  [hi|lo]
__device__ __align__(16) __nv_bfloat16 g_WX[(size_t)VOCAB * KXS];   // W_fc [hi|lo]
__device__ __align__(16) __nv_bfloat16 g_EX[(size_t)MTOT * KXS];    // emb[tok] [hi|lo]
__device__ __align__(16) __nv_bfloat16 g_WIX[(size_t)G4 * KXS];     // W_ih [hi|lo]

// ---------------- helpers ----------------
__device__ __forceinline__ ull pack2(float lo, float hi) {
    ull r; asm("mov.b64 %0, {%1, %2};" : "=l"(r) : "f"(lo), "f"(hi)); return r;
}
__device__ __forceinline__ void unpack2(ull v, float& lo, float& hi) {
    unsigned a, b; asm("mov.b64 {%0, %1}, %2;" : "=r"(a), "=r"(b) : "l"(v));
    lo = __uint_as_float(a); hi = __uint_as_float(b);
}
__device__ __forceinline__ void ffma2(ull& acc, ull a, ull b) {
    asm("fma.rn.f32x2 %0, %1, %2, %0;" : "+l"(acc) : "l"(a), "l"(b));
}
__device__ __forceinline__ ull d2u(double d) { return (ull)__double_as_longlong(d); }
__device__ __forceinline__ uint32_t smem_u32(const void* p) {
    uint32_t a;
    asm("{ .reg .u64 t; cvta.to.shared.u64 t, %1; cvt.u32.u64 %0, t; }" : "=r"(a) : "l"(p));
    return a;
}
__device__ __forceinline__ void cp16(uint32_t saddr, const void* gaddr) {
    asm volatile("cp.async.cg.shared.global [%0], [%1], 16;" :: "r"(saddr), "l"(gaddr));
}
__device__ __forceinline__ uint4 ldsm_x4(uint32_t addr) {
    uint4 r;
    asm volatile("ldmatrix.sync.aligned.m8n8.x4.shared.b16 {%0,%1,%2,%3}, [%4];"
                 : "=r"(r.x), "=r"(r.y), "=r"(r.z), "=r"(r.w) : "r"(addr));
    return r;
}
__device__ __forceinline__ void mma16816(float* c, uint4 a, uint32_t b0, uint32_t b1) {
    asm volatile(
        "mma.sync.aligned.m16n8k16.row.col.f32.bf16.bf16.f32 "
        "{%0,%1,%2,%3}, {%4,%5,%6,%7}, {%8,%9}, {%0,%1,%2,%3};"
        : "+f"(c[0]), "+f"(c[1]), "+f"(c[2]), "+f"(c[3])
        : "r"(a.x), "r"(a.y), "r"(a.z), "r"(a.w), "r"(b0), "r"(b1));
}

// ================= HMMA GEMM: C = A.B^T (+bias), virtual K'=1536 over [hi|lo] storage =====
// R13-proven shape: CTA 128m x 128n, 256 threads (8 warps = 2m x 4n), 3-stage pipeline.
// Stage s (0..23): seg = s>>3, off = (s&7)*64.
//   A source col = (seg<2 ? 0 : 512) + off   (A pattern hi,hi,lo)
//   B source col = (seg==1 ? 512 : 0) + off  (B pattern hi,lo,hi)
// => seg0: Ahi*Bhi, seg1: Ahi*Blo, seg2: Alo*Bhi  — identical to folded bf16x3.
#define STAGE_B 32768
#define NPIPE   3
#define GEMM_SMEM (NPIPE * STAGE_B)
#define NSTAGE 24

template <int EPI>
__global__ void __launch_bounds__(256, 2)
mma_gemm(const float* __restrict__ bias0,
         const float* __restrict__ bias1,
         float* __restrict__ out) {
    const __nv_bfloat16* __restrict__ Asrc = (EPI == 0) ? g_HX : g_EX;
    const __nv_bfloat16* __restrict__ Bsrc = (EPI == 0) ? g_WX : g_WIX;

    extern __shared__ char sm[];
    uint32_t smb = smem_u32(sm);
    int tid = threadIdx.x, wid = tid >> 5, lane = tid & 31;
    int i0 = blockIdx.x * 128;
    int v0 = blockIdx.y * 128;
    int m0w = (wid & 1) * 64;
    int n0w = (wid >> 1) * 32;

    int lrow = tid >> 3, lseg = tid & 7;
    int lplane = lseg >> 1, lhalf = lseg & 1;
    const __nv_bfloat16* gA = Asrc + (size_t)(i0 + lrow) * KXS;
    const __nv_bfloat16* gB = Bsrc + (size_t)(v0 + lrow) * KXS;

    auto issue_stage = [&](int s) {
        uint32_t sb = (uint32_t)((s % NPIPE) * STAGE_B);
        int seg = s >> 3, off = (s & 7) * 64;
        int acol = ((seg < 2) ? 0 : 512) + off + lseg * 8;
        int bcol = ((seg == 1) ? 512 : 0) + off + lseg * 8;
#pragma unroll
        for (int i = 0; i < 4; i++) {
            uint32_t ro = (uint32_t)(((lrow + i * 32 + lplane) & 127) * 32)
                        + (uint32_t)(lplane * 4096 + lhalf * 16);
            cp16(smb + sb + ro,         gA + (size_t)i * 32 * KXS + acol);
            cp16(smb + sb + 16384 + ro, gB + (size_t)i * 32 * KXS + bcol);
        }
        asm volatile("cp.async.commit_group;");
    };

    float acc[4][4][4];
#pragma unroll
    for (int a = 0; a < 4; a++)
#pragma unroll
        for (int b = 0; b < 4; b++)
#pragma unroll
            for (int r = 0; r < 4; r++) acc[a][b][r] = 0.0f;

    issue_stage(0);
    issue_stage(1);
    issue_stage(2);

    for (int s = 0; s < NSTAGE; s++) {
        asm volatile("cp.async.wait_group 2;");
        __syncthreads();
        uint32_t base = smb + (uint32_t)((s % NPIPE) * STAGE_B);
#pragma unroll
        for (int p = 0; p < 4; p++) {
            uint32_t abase = base + p * 4096;
            uint32_t bbase = abase + 16384;
            uint32_t brow0 = (uint32_t)(n0w + (lane & 7) + ((lane >> 4) << 3));
            uint32_t bhalf = (uint32_t)((lane >> 3) & 1);
            uint4 bf01 = ldsm_x4(bbase + (((brow0 + p) & 127) * 32) + bhalf * 16);
            uint4 bf23 = ldsm_x4(bbase + (((brow0 + 16 + p) & 127) * 32) + bhalf * 16);
            uint32_t arow = (uint32_t)(m0w + (lane & 15));
            uint32_t ahalf = (uint32_t)(lane >> 4);
            uint4 af[4];
#pragma unroll
            for (int im = 0; im < 4; im++)
                af[im] = ldsm_x4(abase + (((arow + im * 16 + p) & 127) * 32) + ahalf * 16);
#pragma unroll
            for (int im = 0; im < 4; im++) {
                mma16816(acc[im][0], af[im], bf01.x, bf01.y);
                mma16816(acc[im][1], af[im], bf01.z, bf01.w);
                mma16816(acc[im][2], af[im], bf23.x, bf23.y);
                mma16816(acc[im][3], af[im], bf23.z, bf23.w);
            }
        }
        __syncthreads();
        if (s + NPIPE < NSTAGE) issue_stage(s + NPIPE);
        else asm volatile("cp.async.commit_group;");
    }

    // ---------------- epilogue ----------------
    int gm = lane >> 2, gn = 2 * (lane & 3);
    if (EPI == 0) {
#pragma unroll
        for (int im = 0; im < 4; im++) {
#pragma unroll
            for (int jn = 0; jn < 4; jn++) {
                int col = v0 + n0w + jn * 8 + gn;
                float2 bb = *(const float2*)(bias0 + col);
                int row = i0 + m0w + im * 16 + gm;
                float2 o0 = make_float2(acc[im][jn][0] + bb.x, acc[im][jn][1] + bb.y);
                float2 o1 = make_float2(acc[im][jn][2] + bb.x, acc[im][jn][3] + bb.y);
                __stcs((float2*)(out + (size_t)row * VOCAB + col), o0);
                __stcs((float2*)(out + (size_t)(row + 8) * VOCAB + col), o1);
            }
        }
    } else {
#pragma unroll
        for (int im = 0; im < 4; im++) {
#pragma unroll
            for (int jn = 0; jn < 4; jn++) {
                int col = v0 + n0w + jn * 8 + gn;
                float b0 = bias0[col] + bias1[col];
                float b1 = bias0[col + 1] + bias1[col + 1];
                int r0 = i0 + m0w + im * 16 + gm;
                int r1 = r0 + 8;
                size_t base0 = (size_t)(r0 >> 5) * (G4 * BATCH) + (r0 & 31);
                size_t base1 = (size_t)(r1 >> 5) * (G4 * BATCH) + (r1 & 31);
                g_XPt[base0 + (size_t)col * 32]       = acc[im][jn][0] + b0;
                g_XPt[base0 + (size_t)(col + 1) * 32] = acc[im][jn][1] + b1;
                g_XPt[base1 + (size_t)col * 32]       = acc[im][jn][2] + b0;
                g_XPt[base1 + (size_t)(col + 1) * 32] = acc[im][jn][3] + b1;
            }
        }
    }
}

// ================= split kernels (fp32 -> bf16 [hi|lo], compact) =================
__device__ __forceinline__ void split_row(const float4 w, __nv_bfloat16* row, int k) {
    __nv_bfloat16 h0 = __float2bfloat16_rn(w.x), h1 = __float2bfloat16_rn(w.y);
    __nv_bfloat16 h2 = __float2bfloat16_rn(w.z), h3 = __float2bfloat16_rn(w.w);
    __nv_bfloat16 l0 = __float2bfloat16_rn(w.x - __bfloat162float(h0));
    __nv_bfloat16 l1 = __float2bfloat16_rn(w.y - __bfloat162float(h1));
    __nv_bfloat16 l2 = __float2bfloat16_rn(w.z - __bfloat162float(h2));
    __nv_bfloat16 l3 = __float2bfloat16_rn(w.w - __bfloat162float(h3));
    ushort4 hv = make_ushort4(__bfloat16_as_ushort(h0), __bfloat16_as_ushort(h1),
                              __bfloat16_as_ushort(h2), __bfloat16_as_ushort(h3));
    ushort4 lv = make_ushort4(__bfloat16_as_ushort(l0), __bfloat16_as_ushort(l1),
                              __bfloat16_as_ushort(l2), __bfloat16_as_ushort(l3));
    *(ushort4*)(row + k)       = hv;
    *(ushort4*)(row + 512 + k) = lv;
}

__global__ void split_W(const float* __restrict__ W_fc) {
    int idx = blockIdx.x * 256 + threadIdx.x;        // 32000*128
    int v = idx >> 7, q = idx & 127;
    float4 w = *(const float4*)(W_fc + (size_t)v * HDIM + q * 4);
    split_row(w, g_WX + (size_t)v * KXS, q * 4);
}
__global__ void split_WI(const float* __restrict__ W_ih) {
    int idx = blockIdx.x * 256 + threadIdx.x;        // 2048*128
    int v = idx >> 7, q = idx & 127;
    float4 w = *(const float4*)(W_ih + (size_t)v * HDIM + q * 4);
    split_row(w, g_WIX + (size_t)v * KXS, q * 4);
}
__global__ void split_E(const int* __restrict__ tokens, const float* __restrict__ emb) {
    int idx = blockIdx.x * 256 + threadIdx.x;        // 2048*128
    int i = idx >> 7, q = idx & 127;
    int tok = tokens[i];
    float4 w = *(const float4*)(emb + (size_t)tok * HDIM + q * 4);
    split_row(w, g_EX + (size_t)i * KXS, q * 4);
}

// ================= one-time W_hh transpose =================
__global__ void prep_W4(const float* __restrict__ W_hh) {
    int idx = blockIdx.x * 256 + threadIdx.x;
    int j = idx >> 9, k = idx & 511;
    g_W4[(size_t)j * 512 + k] = make_float4(
        W_hh[(size_t)(0 * 512 + j) * 512 + k],
        W_hh[(size_t)(1 * 512 + j) * 512 + k],
        W_hh[(size_t)(2 * 512 + j) * 512 + k],
        W_hh[(size_t)(3 * 512 + j) * 512 + k]);
}

// ================= init =================
__global__ void init_kernel(const float* __restrict__ h0, const float* __restrict__ c0) {
    int idx = blockIdx.x * blockDim.x + threadIdx.x;
    if (idx < BATCH * HDIM) {
        int j = idx >> 5, b = idx & 31;
        ((float*)g_hT4[0])[(j >> 2) * 128 + b * 4 + (j & 3)] = h0[b * HDIM + j];
        g_cT[j * 32 + b] = c0[b * HDIM + j];
    }
}

// ================= recurrent step: K-split x8, CTA = one j (R13-proven inner loop) =====
// Pointwise now also writes the bf16 hi/lo split of htmp straight into g_HX
// (split_H fused away; g_H eliminated).
__global__ void __launch_bounds__(256, 4)
recurrent_kernel(const int* __restrict__ tokens, int t) {
    __shared__ float4 sred[8][32];
    int tid = threadIdx.x;
    int w = tid >> 5, b = tid & 31;
    int j = blockIdx.x;

    const float4*  hT = g_hT4[t & 1];
    const double2* wp = (const double2*)(g_W4 + (size_t)j * 512) + (size_t)w * 64;
    const float4*  hp = hT + w * 16 * 32;

    ull aif0 = pack2(0.0f, 0.0f), aif1 = pack2(0.0f, 0.0f);
    ull ago0 = pack2(0.0f, 0.0f), ago1 = pack2(0.0f, 0.0f);

#pragma unroll
    for (int kk = 0; kk < 16; kk++) {
        float4  h4 = hp[kk * 32 + b];
        double2 w0 = wp[kk * 4 + 0];
        double2 w1 = wp[kk * 4 + 1];
        double2 w2 = wp[kk * 4 + 2];
        double2 w3 = wp[kk * 4 + 3];
        ull hx = pack2(h4.x, h4.x), hy = pack2(h4.y, h4.y);
        ull hz = pack2(h4.z, h4.z), hw = pack2(h4.w, h4.w);
        ffma2(aif0, hx, d2u(w0.x));
        ffma2(ago0, hx, d2u(w0.y));
        ffma2(aif1, hy, d2u(w1.x));
        ffma2(ago1, hy, d2u(w1.y));
        ffma2(aif0, hz, d2u(w2.x));
        ffma2(ago0, hz, d2u(w2.y));
        ffma2(aif1, hw, d2u(w3.x));
        ffma2(ago1, hw, d2u(w3.y));
    }

    float ia, fa, ib, fb, ga, oa, gb, ob;
    unpack2(aif0, ia, fa); unpack2(aif1, ib, fb);
    unpack2(ago0, ga, oa); unpack2(ago1, gb, ob);
    sred[w][b] = make_float4(ia + ib, fa + fb, ga + gb, oa + ob);
    __syncthreads();

    if (w == 0) {
        float4 acc4 = sred[0][b];
#pragma unroll
        for (int q = 1; q < 8; q++) {
            float4 s = sred[q][b];
            acc4.x += s.x; acc4.y += s.y; acc4.z += s.z; acc4.w += s.w;
        }
        size_t xb = (size_t)t * (G4 * BATCH) + (size_t)b;
        float ig = acc4.x + g_XPt[xb + (size_t)(0 * 512 + j) * 32];
        float fg = acc4.y + g_XPt[xb + (size_t)(1 * 512 + j) * 32];
        float gg = acc4.z + g_XPt[xb + (size_t)(2 * 512 + j) * 32];
        float og = acc4.w + g_XPt[xb + (size_t)(3 * 512 + j) * 32];

        float iv = 1.0f / (1.0f + expf(-ig));
        float fv = 1.0f / (1.0f + expf(-fg));
        float gv = tanhf(gg);
        float ov = 1.0f / (1.0f + expf(-og));

        float cold = g_cT[j * 32 + b];
        float ctmp = fv * cold + iv * gv;
        float htmp = ov * tanhf(ctmp);
        bool  msk  = tokens[t * BATCH + b] != 0;   // PAD = 0

        // fused bf16 hi/lo split of the tentative hidden -> g_HX
        __nv_bfloat16 hh = __float2bfloat16_rn(htmp);
        __nv_bfloat16 hl = __float2bfloat16_rn(htmp - __bfloat162float(hh));
        size_t hrow = ((size_t)t * BATCH + b) * KXS;
        g_HX[hrow + j]       = hh;
        g_HX[hrow + 512 + j] = hl;

        float hold = ((const float*)hT)[(j >> 2) * 128 + b * 4 + (j & 3)];
        ((float*)g_hT4[(t + 1) & 1])[(j >> 2) * 128 + b * 4 + (j & 3)] = msk ? htmp : hold;
        g_cT[j * 32 + b] = msk ? ctmp : cold;
    }
}

// ================= launch =================
extern "C" void kernel_launch(void* const* d_in, const int* in_sizes, int n_in,
                              void* d_out, int out_size) {
    const int*   tokens = (const int*)d_in[0];
    const float* emb    = (const float*)d_in[1];
    const float* W_ih   = (const float*)d_in[2];
    const float* W_hh   = (const float*)d_in[3];
    const float* b_ih   = (const float*)d_in[4];
    const float* b_hh   = (const float*)d_in[5];
    const float* W_fc   = (const float*)d_in[6];
    const float* b_fc   = (const float*)d_in[7];
    const float* h0     = (const float*)d_in[8];
    const float* c0     = (const float*)d_in[9];
    float* out = (float*)d_out;

    cudaFuncSetAttribute(mma_gemm<0>, cudaFuncAttributeMaxDynamicSharedMemorySize, GEMM_SMEM);
    cudaFuncSetAttribute(mma_gemm<1>, cudaFuncAttributeMaxDynamicSharedMemorySize, GEMM_SMEM);

    init_kernel<<<64, 256>>>(h0, c0);
    prep_W4<<<1024, 256>>>(W_hh);
    split_W<<<16000, 256>>>(W_fc);
    split_WI<<<1024, 256>>>(W_ih);
    split_E<<<1024, 256>>>(tokens, emb);

    // XPt = emb[tok] @ W_ih^T + (b_ih + b_hh):  M=2048, N=2048 (HMMA bf16x3, compact)
    mma_gemm<1><<<dim3(16, 16), 256, GEMM_SMEM>>>(b_ih, b_hh, nullptr);

    // 64 LSTM steps, one launch each (proven kernel; writes g_HX directly)
    for (int t = 0; t < T_STEPS; t++)
        recurrent_kernel<<<512, 256>>>(tokens, t);

    // out = H @ W_fc^T + b_fc:  M=2048, N=32000 (HMMA bf16x3, compact, R13 tile)
    mma_gemm<0><<<dim3(16, 250), 256, GEMM_SMEM>>>(b_fc, nullptr, out);
}